// round 2
// baseline (speedup 1.0000x reference)
#include <cuda_runtime.h>
#include <cstdint>

// Problem constants
#define N_TOK   8192
#define DIM     4096
#define N_EXP   64
#define TOPK    2
#define CAP     160           // ceil(1.25 * 8192 / 64)
#define NEC     ((size_t)N_TOK * N_EXP * CAP)   // 83,886,080

// Scratch (device globals; no allocation allowed)
__device__ int   g_topk_idx[N_TOK * TOPK];
__device__ float g_topk_val[N_TOK * TOPK];
__device__ int   g_counts[N_EXP];
__device__ float g_colsum[N_EXP];

// packed fp32x2 FMA (sm_103a FFMA2): d.lo += a.lo*b.lo, d.hi += a.hi*b.hi
__device__ __forceinline__ void fma2(unsigned long long& d,
                                     unsigned long long a,
                                     unsigned long long b) {
    asm("fma.rn.f32x2 %0, %1, %2, %0;" : "+l"(d) : "l"(a), "l"(b));
}

__device__ __forceinline__ float ull_lo(unsigned long long a) {
    return __uint_as_float((unsigned)(a & 0xffffffffu));
}
__device__ __forceinline__ float ull_hi(unsigned long long a) {
    return __uint_as_float((unsigned)(a >> 32));
}

// ---------------------------------------------------------------------------
// Kernel 1: GEMM (logits = x @ gate_w^T) + softmax (probs out) + top-2.
// Grid: 128 blocks x 256 threads. Block computes 64 rows x 64 experts.
// K-loop in chunks of 32 with register prefetch. Accumulators are f32x2
// holding (even-k, odd-k) partial sums, combined at the end.
// ---------------------------------------------------------------------------
__global__ __launch_bounds__(256)
void gemm_topk_kernel(const float* __restrict__ x,
                      const float* __restrict__ gw,
                      float* __restrict__ probs_out) {
    __shared__ float smem[64 * 66];      // 16.9 KB; reused: Xs(2048)+Ws(2048) then logits(64x66)
    float* Xs = smem;                    // [row][k] 64x32, 128B/row, XOR-swizzled by (row>>3)&7
    float* Ws = smem + 2048;             // [exp][k] 64x32, XOR-swizzled by exp&7

    const int tid = threadIdx.x;
    const int rowBase = blockIdx.x * 64;

    const int rg = tid & 7;              // 8 row-groups of 8 rows
    const int cg = tid >> 3;             // 32 col-groups of 2 cols
    const int c0 = cg * 2, c1 = c0 + 1;
    const int row0 = rg * 8;
    const int xswz = rg << 2;            // (row>>3)&7 == rg for this thread's rows (float units)

    // staging indices for global->smem copies (each thread moves 2 float4 of X and W)
    const int fA = tid, fB = tid + 256;
    const int rA = fA >> 3, kA = (fA & 7) * 4;
    const int rB = fB >> 3, kB = (fB & 7) * 4;
    const int xsA = (rA * 32 + kA) ^ (((rA >> 3) & 7) << 2);
    const int xsB = (rB * 32 + kB) ^ (((rB >> 3) & 7) << 2);
    const int wsA = (rA * 32 + kA) ^ ((rA & 7) << 2);
    const int wsB = (rB * 32 + kB) ^ ((rB & 7) << 2);

    const float* xg = x + (size_t)rowBase * DIM;

    unsigned long long acc[8][2];
#pragma unroll
    for (int r = 0; r < 8; r++) { acc[r][0] = 0ull; acc[r][1] = 0ull; }

    float4 xr0, xr1, wr0, wr1;
    // prologue load (chunk 0)
    xr0 = *(const float4*)&xg[(size_t)rA * DIM + kA];
    xr1 = *(const float4*)&xg[(size_t)rB * DIM + kB];
    wr0 = *(const float4*)&gw[(size_t)rA * DIM + kA];
    wr1 = *(const float4*)&gw[(size_t)rB * DIM + kB];

    for (int kc = 0; kc < DIM / 32; kc++) {
        *(float4*)&Xs[xsA] = xr0;
        *(float4*)&Xs[xsB] = xr1;
        *(float4*)&Ws[wsA] = wr0;
        *(float4*)&Ws[wsB] = wr1;
        __syncthreads();

        if (kc + 1 < DIM / 32) {
            const int ko = (kc + 1) * 32;
            xr0 = *(const float4*)&xg[(size_t)rA * DIM + ko + kA];
            xr1 = *(const float4*)&xg[(size_t)rB * DIM + ko + kB];
            wr0 = *(const float4*)&gw[(size_t)rA * DIM + ko + kA];
            wr1 = *(const float4*)&gw[(size_t)rB * DIM + ko + kB];
        }

#pragma unroll
        for (int k = 0; k < 32; k += 4) {
            ulonglong2 B0 = *(const ulonglong2*)&Ws[(c0 * 32 + k) ^ ((c0 & 7) << 2)];
            ulonglong2 B1 = *(const ulonglong2*)&Ws[(c1 * 32 + k) ^ ((c1 & 7) << 2)];
#pragma unroll
            for (int r = 0; r < 8; r++) {
                ulonglong2 A = *(const ulonglong2*)&Xs[((row0 + r) * 32 + k) ^ xswz];
                fma2(acc[r][0], A.x, B0.x);
                fma2(acc[r][0], A.y, B0.y);
                fma2(acc[r][1], A.x, B1.x);
                fma2(acc[r][1], A.y, B1.y);
            }
        }
        __syncthreads();
    }

    // write logits to smem (stride 66 to dodge bank conflicts)
    float* lg = smem;
#pragma unroll
    for (int r = 0; r < 8; r++) {
        lg[(row0 + r) * 66 + c0] = ull_lo(acc[r][0]) + ull_hi(acc[r][0]);
        lg[(row0 + r) * 66 + c1] = ull_lo(acc[r][1]) + ull_hi(acc[r][1]);
    }
    __syncthreads();

    // per-row softmax + top-2: warp w handles rows w*8 .. w*8+7
    const int lane = tid & 31;
    const int w = tid >> 5;
    for (int rr = 0; rr < 8; rr++) {
        const int r = w * 8 + rr;
        float2 lv = *(float2*)&lg[r * 66 + lane * 2];
        float v0 = lv.x, v1 = lv.y;

        float m = fmaxf(v0, v1);
#pragma unroll
        for (int off = 16; off; off >>= 1)
            m = fmaxf(m, __shfl_xor_sync(0xffffffffu, m, off));

        float e0 = expf(v0 - m), e1 = expf(v1 - m);
        float s = e0 + e1;
#pragma unroll
        for (int off = 16; off; off >>= 1)
            s += __shfl_xor_sync(0xffffffffu, s, off);
        float inv = 1.0f / s;

        const int gtok = rowBase + r;
        *(float2*)&probs_out[(size_t)gtok * N_EXP + lane * 2] =
            make_float2(e0 * inv, e1 * inv);

        // top-1 (ties -> lower index, matching jax top_k)
        float cv; int ci;
        if (v0 >= v1) { cv = v0; ci = lane * 2; } else { cv = v1; ci = lane * 2 + 1; }
#pragma unroll
        for (int off = 16; off; off >>= 1) {
            float ov = __shfl_xor_sync(0xffffffffu, cv, off);
            int   oi = __shfl_xor_sync(0xffffffffu, ci, off);
            if (ov > cv || (ov == cv && oi < ci)) { cv = ov; ci = oi; }
        }
        const float t1v = cv; const int t1i = ci;

        // top-2: lane holding t1i offers its other column
        if (lane * 2 == t1i)          { cv = v1; ci = lane * 2 + 1; }
        else if (lane * 2 + 1 == t1i) { cv = v0; ci = lane * 2; }
        else if (v0 >= v1)            { cv = v0; ci = lane * 2; }
        else                          { cv = v1; ci = lane * 2 + 1; }
#pragma unroll
        for (int off = 16; off; off >>= 1) {
            float ov = __shfl_xor_sync(0xffffffffu, cv, off);
            int   oi = __shfl_xor_sync(0xffffffffu, ci, off);
            if (ov > cv || (ov == cv && oi < ci)) { cv = ov; ci = oi; }
        }
        const float t2v = cv; const int t2i = ci;

        if (lane == 0) {
            // normalized vals: p1/(p1+p2) = 1/(1+exp(l2-l1)), p2 share = exp/(1+exp)
            float rr2 = expf(t2v - t1v);
            float inv2 = 1.0f / (1.0f + rr2);
            g_topk_idx[2 * gtok]     = t1i;
            g_topk_idx[2 * gtok + 1] = t2i;
            g_topk_val[2 * gtok]     = inv2;
            g_topk_val[2 * gtok + 1] = rr2 * inv2;
        }
    }
}

// ---------------------------------------------------------------------------
// Kernel 2: one block per expert. Ordered prefix count over the flat (N*K)
// assignment list (token-major, matching the reference cumsum), scatter kept
// entries into dispatch_mask / combine_weights, record total count, and the
// deterministic column-sum of probs for the aux loss.
// ---------------------------------------------------------------------------
__global__ __launch_bounds__(256)
void scan_scatter_kernel(float* __restrict__ mask,
                         float* __restrict__ combine,
                         const float* __restrict__ probs) {
    const int e = blockIdx.x;
    const int tid = threadIdx.x;
    const int lane = tid & 31;
    const int w = tid >> 5;
    __shared__ int   wsum[8];
    __shared__ float fsum[8];

    int running = 0;
    for (int base = 0; base < N_TOK * TOPK; base += 256) {
        const int i = base + tid;
        const bool m = (g_topk_idx[i] == e);
        const unsigned bal = __ballot_sync(0xffffffffu, m);
        if (lane == 0) wsum[w] = __popc(bal);
        __syncthreads();
        int woff = 0, tot = 0;
#pragma unroll
        for (int j = 0; j < 8; j++) {
            int t = wsum[j];
            if (j < w) woff += t;
            tot += t;
        }
        if (m) {
            const int slot = running + woff + __popc(bal & ((1u << lane) - 1u));
            if (slot < CAP) {
                const int tok = i >> 1;
                const size_t o = (size_t)tok * (N_EXP * CAP) + e * CAP + slot;
                mask[o] = 1.0f;
                combine[o] = g_topk_val[i];
            }
        }
        running += tot;
        __syncthreads();
    }
    if (tid == 0) g_counts[e] = running;

    // deterministic column sum of probs[:, e]
    float s = 0.0f;
    for (int t = tid; t < N_TOK; t += 256)
        s += probs[(size_t)t * N_EXP + e];
#pragma unroll
    for (int off = 16; off; off >>= 1)
        s += __shfl_xor_sync(0xffffffffu, s, off);
    if (lane == 0) fsum[w] = s;
    __syncthreads();
    if (tid == 0) {
        float t = 0.0f;
#pragma unroll
        for (int j = 0; j < 8; j++) t += fsum[j];
        g_colsum[e] = t;
    }
}

// ---------------------------------------------------------------------------
// Kernel 3: load-balancing loss (scalar).
// ---------------------------------------------------------------------------
__global__ void loss_kernel(float* __restrict__ out_loss) {
    const int e = threadIdx.x;   // 64 threads
    __shared__ float sh[N_EXP];
    sh[e] = ((float)g_counts[e] / (float)(N_TOK * TOPK)) *
            (g_colsum[e] / (float)N_TOK);
    __syncthreads();
    if (e == 0) {
        float s = 0.0f;
#pragma unroll
        for (int j = 0; j < N_EXP; j++) s += sh[j];
        out_loss[0] = 0.01f * (float)N_EXP * s;
    }
}

// ---------------------------------------------------------------------------
extern "C" void kernel_launch(void* const* d_in, const int* in_sizes, int n_in,
                              void* d_out, int out_size) {
    const float* x  = (const float*)d_in[0];
    const float* gw = (const float*)d_in[1];
    if (n_in >= 2 && in_sizes[0] < in_sizes[1]) {  // robustness vs input ordering
        const float* t = x; x = gw; gw = t;
    }
    float* out = (float*)d_out;

    // layout: [dispatch_mask (N,E,C)] [combine_weights (N,E,C)] [probs (N,E)] [loss]
    float* mask    = out;
    float* combine = out + NEC;
    float* probs   = out + 2 * NEC;
    float* loss    = out + 2 * NEC + (size_t)N_TOK * N_EXP;

    cudaMemsetAsync(out, 0, 2 * NEC * sizeof(float));
    gemm_topk_kernel<<<N_TOK / 64, 256>>>(x, gw, probs);
    scan_scatter_kernel<<<N_EXP, 256>>>(mask, combine, probs);
    loss_kernel<<<1, N_EXP>>>(loss);
}